// round 17
// baseline (speedup 1.0000x reference)
#include <cuda_runtime.h>
#include <cuda_fp16.h>
#include <math.h>

#define Bn 4096
#define Tn 64

typedef unsigned long long ull;

// ---------------- device scratch ----------------
// g_x2h: [t][chunk64][4096 halves in m16n8k16 A-fragment order, mtg-major]
__device__ __half g_x2h[(size_t)Tn * Bn * 64];

__device__ __forceinline__ float tanha(float x) {
    float r; asm("tanh.approx.f32 %0, %1;" : "=f"(r) : "f"(x)); return r;
}
__device__ __forceinline__ float sigt(float x) {
    return fmaf(tanha(0.5f * x), 0.5f, 0.5f);
}
__device__ __forceinline__ unsigned h2u(float lo, float hi) {
    __half2 h = __floats2half2_rn(lo, hi);
    return *(unsigned*)&h;
}
__device__ __forceinline__ void mma_f16(float* c, uint4 a, uint2 b) {
    asm volatile(
        "mma.sync.aligned.m16n8k16.row.col.f32.f16.f16.f32 "
        "{%0,%1,%2,%3}, {%4,%5,%6,%7}, {%8,%9}, {%0,%1,%2,%3};"
        : "+f"(c[0]), "+f"(c[1]), "+f"(c[2]), "+f"(c[3])
        : "r"(a.x), "r"(a.y), "r"(a.z), "r"(a.w), "r"(b.x), "r"(b.y));
}

#define XPH 72   // trunk sX pad (halves per row; 64-col chunk + 8 pad)
#define AP 104   // trunk sA2 pad

// =====================================================================
// Kernel 1: MLP trunk via fp16 mma. CTA = (chunk64, tpair): 64 seqs x 2 t.
// obs streamed in two K=64 chunks -> smem 75.3 KB -> 3 CTAs/SM.
// Output written in fragment order, coalesced.
// =====================================================================
__global__ void __launch_bounds__(256, 3) trunk_kernel(
    const float* __restrict__ obs, const float* __restrict__ act,
    const float* __restrict__ W1, const float* __restrict__ b1,
    const float* __restrict__ g1, const float* __restrict__ be1,
    const float* __restrict__ W2, const float* __restrict__ b2,
    const float* __restrict__ g2, const float* __restrict__ be2)
{
    extern __shared__ char smc[];
    uint2*  B1   = (uint2*)smc;                      // 2048 uint2 (16 KB)
    uint2*  B2   = (uint2*)(smc + 16384);            // 1536 uint2 (12 KB)
    __half* sX   = (__half*)(smc + 28672);           // 128 x XPH (18 KB)
    __half* sA2  = (__half*)(smc + 28672 + 128*XPH*2);// 128 x AP (26 KB)
    float*  sP   = (float*)(smc + 28672 + 128*XPH*2 + 128*AP*2); // 384

    const int tid = threadIdx.x;
    const int l = tid & 31, w = tid >> 5;
    const int chunk = blockIdx.x >> 5, tpair = blockIdx.x & 31;

    // ---- W1 -> fp16 B-frags [nt8][kt8][lane32] ----
#pragma unroll
    for (int q = 0; q < 8; ++q) {
        int s = tid + q * 256;
        int l2 = s & 31, kt = (s >> 5) & 7, nt = s >> 8;
        int k0 = kt * 16 + 2 * (l2 & 3), n = nt * 8 + (l2 >> 2);
        uint2 b;
        b.x = h2u(W1[k0 * 64 + n],       W1[(k0 + 1) * 64 + n]);
        b.y = h2u(W1[(k0 + 8) * 64 + n], W1[(k0 + 9) * 64 + n]);
        B1[s] = b;
    }
    // ---- W2 -> fp16 B-frags [nt8][kt6][lane32] ----
#pragma unroll
    for (int q = 0; q < 6; ++q) {
        int s = tid + q * 256;
        int l2 = s & 31, r = s >> 5;
        int kt = r % 6, nt = r / 6;
        int k0 = kt * 16 + 2 * (l2 & 3), n = nt * 8 + (l2 >> 2);
        uint2 b;
        b.x = h2u(W2[k0 * 64 + n],       W2[(k0 + 1) * 64 + n]);
        b.y = h2u(W2[(k0 + 8) * 64 + n], W2[(k0 + 9) * 64 + n]);
        B2[s] = b;
    }
    if (tid < 64) {
        sP[tid]       = b1[tid];  sP[64 + tid]  = g1[tid];  sP[128 + tid] = be1[tid];
        sP[192 + tid] = b2[tid];  sP[256 + tid] = g2[tid];  sP[320 + tid] = be2[tid];
    }
    // ---- action -> sA2 cols 64..95 ----
#pragma unroll
    for (int q = 0; q < 4; ++q) {
        int f = tid + q * 256;
        int row = f >> 3, c8 = f & 7;
        int s = row & 63, tj = row >> 6;
        size_t grow = ((size_t)(chunk * 64 + s)) * 64 + tpair * 2 + tj;
        float4 v = *(const float4*)(act + grow * 32 + c8 * 4);
        uint2 hv; hv.x = h2u(v.x, v.y); hv.y = h2u(v.z, v.w);
        *(uint2*)(sA2 + row * AP + 64 + c8 * 4) = hv;
    }
    // ---- obs chunk 0 (K cols 0..63) -> sX ----
#pragma unroll
    for (int q = 0; q < 8; ++q) {
        int f = tid + q * 256;
        int row = f >> 4, c4 = f & 15;
        int s = row & 63, tj = row >> 6;
        size_t grow = ((size_t)(chunk * 64 + s)) * 64 + tpair * 2 + tj;
        float4 v = *(const float4*)(obs + grow * 128 + c4 * 4);
        uint2 hv; hv.x = h2u(v.x, v.y); hv.y = h2u(v.z, v.w);
        *(uint2*)(sX + row * XPH + c4 * 4) = hv;
    }
    __syncthreads();

    const int q4 = l & 3, rlq = l >> 2;
    const int ar = w * 16 + rlq;

    // ---- GEMM1 part A (B1 kt 0..3 on chunk 0) ----
    float acc[8][4];
#pragma unroll
    for (int nt = 0; nt < 8; ++nt) {
        int c0 = nt * 8 + 2 * q4;
        acc[nt][0] = sP[c0]; acc[nt][1] = sP[c0 + 1];
        acc[nt][2] = sP[c0]; acc[nt][3] = sP[c0 + 1];
    }
#pragma unroll
    for (int kt = 0; kt < 4; ++kt) {
        int cb = kt * 16 + 2 * q4;
        uint4 a;
        a.x = *(const unsigned*)(sX + ar * XPH + cb);
        a.y = *(const unsigned*)(sX + (ar + 8) * XPH + cb);
        a.z = *(const unsigned*)(sX + ar * XPH + cb + 8);
        a.w = *(const unsigned*)(sX + (ar + 8) * XPH + cb + 8);
#pragma unroll
        for (int nt = 0; nt < 8; ++nt)
            mma_f16(acc[nt], a, B1[(nt * 8 + kt) * 32 + l]);
    }
    __syncthreads();   // chunk-0 reads done

    // ---- obs chunk 1 (K cols 64..127) -> sX ----
#pragma unroll
    for (int q = 0; q < 8; ++q) {
        int f = tid + q * 256;
        int row = f >> 4, c4 = f & 15;
        int s = row & 63, tj = row >> 6;
        size_t grow = ((size_t)(chunk * 64 + s)) * 64 + tpair * 2 + tj;
        float4 v = *(const float4*)(obs + grow * 128 + 64 + c4 * 4);
        uint2 hv; hv.x = h2u(v.x, v.y); hv.y = h2u(v.z, v.w);
        *(uint2*)(sX + row * XPH + c4 * 4) = hv;
    }
    __syncthreads();

    // ---- GEMM1 part B (B1 kt 4..7 on chunk 1) ----
#pragma unroll
    for (int kt = 4; kt < 8; ++kt) {
        int cb = (kt - 4) * 16 + 2 * q4;
        uint4 a;
        a.x = *(const unsigned*)(sX + ar * XPH + cb);
        a.y = *(const unsigned*)(sX + (ar + 8) * XPH + cb);
        a.z = *(const unsigned*)(sX + ar * XPH + cb + 8);
        a.w = *(const unsigned*)(sX + (ar + 8) * XPH + cb + 8);
#pragma unroll
        for (int nt = 0; nt < 8; ++nt)
            mma_f16(acc[nt], a, B1[(nt * 8 + kt) * 32 + l]);
    }

    // ---- LN1 + relu -> sA2 (half) ----
    {
        float sl = 0.f, ql = 0.f, sh = 0.f, qh = 0.f;
#pragma unroll
        for (int nt = 0; nt < 8; ++nt) {
            sl += acc[nt][0] + acc[nt][1];
            ql += acc[nt][0] * acc[nt][0] + acc[nt][1] * acc[nt][1];
            sh += acc[nt][2] + acc[nt][3];
            qh += acc[nt][2] * acc[nt][2] + acc[nt][3] * acc[nt][3];
        }
#pragma unroll
        for (int o = 1; o <= 2; o <<= 1) {
            sl += __shfl_xor_sync(0xffffffffu, sl, o);
            ql += __shfl_xor_sync(0xffffffffu, ql, o);
            sh += __shfl_xor_sync(0xffffffffu, sh, o);
            qh += __shfl_xor_sync(0xffffffffu, qh, o);
        }
        float ml = sl * 0.015625f, vl = ql * 0.015625f - ml * ml;
        float mh = sh * 0.015625f, vh = qh * 0.015625f - mh * mh;
        float il = rsqrtf(vl + 1e-12f), ih = rsqrtf(vh + 1e-12f);
#pragma unroll
        for (int nt = 0; nt < 8; ++nt) {
            int c0 = nt * 8 + 2 * q4;
            float g0 = sP[64 + c0], g1v = sP[64 + c0 + 1];
            float e0 = sP[128 + c0], e1v = sP[128 + c0 + 1];
            float zl0 = fmaxf((acc[nt][0] - ml) * il * g0  + e0,  0.f);
            float zl1 = fmaxf((acc[nt][1] - ml) * il * g1v + e1v, 0.f);
            float zh0 = fmaxf((acc[nt][2] - mh) * ih * g0  + e0,  0.f);
            float zh1 = fmaxf((acc[nt][3] - mh) * ih * g1v + e1v, 0.f);
            *(unsigned*)(sA2 + ar * AP + c0)       = h2u(zl0, zl1);
            *(unsigned*)(sA2 + (ar + 8) * AP + c0) = h2u(zh0, zh1);
        }
    }
    __syncthreads();

    // ---- GEMM2: K=96 -> 6 kt ----
    float a2[8][4];
#pragma unroll
    for (int nt = 0; nt < 8; ++nt) {
        int c0 = nt * 8 + 2 * q4;
        a2[nt][0] = sP[192 + c0]; a2[nt][1] = sP[192 + c0 + 1];
        a2[nt][2] = sP[192 + c0]; a2[nt][3] = sP[192 + c0 + 1];
    }
#pragma unroll
    for (int kt = 0; kt < 6; ++kt) {
        int cb = kt * 16 + 2 * q4;
        uint4 a;
        a.x = *(const unsigned*)(sA2 + ar * AP + cb);
        a.y = *(const unsigned*)(sA2 + (ar + 8) * AP + cb);
        a.z = *(const unsigned*)(sA2 + ar * AP + cb + 8);
        a.w = *(const unsigned*)(sA2 + (ar + 8) * AP + cb + 8);
#pragma unroll
        for (int nt = 0; nt < 8; ++nt)
            mma_f16(a2[nt], a, B2[(nt * 6 + kt) * 32 + l]);
    }

    // ---- LN2 + relu + fp16 -> stage sX (64 cols) ----
    {
        float sl = 0.f, ql = 0.f, sh = 0.f, qh = 0.f;
#pragma unroll
        for (int nt = 0; nt < 8; ++nt) {
            sl += a2[nt][0] + a2[nt][1];
            ql += a2[nt][0] * a2[nt][0] + a2[nt][1] * a2[nt][1];
            sh += a2[nt][2] + a2[nt][3];
            qh += a2[nt][2] * a2[nt][2] + a2[nt][3] * a2[nt][3];
        }
#pragma unroll
        for (int o = 1; o <= 2; o <<= 1) {
            sl += __shfl_xor_sync(0xffffffffu, sl, o);
            ql += __shfl_xor_sync(0xffffffffu, ql, o);
            sh += __shfl_xor_sync(0xffffffffu, sh, o);
            qh += __shfl_xor_sync(0xffffffffu, qh, o);
        }
        float ml = sl * 0.015625f, vl = ql * 0.015625f - ml * ml;
        float mh = sh * 0.015625f, vh = qh * 0.015625f - mh * mh;
        float il = rsqrtf(vl + 1e-12f), ih = rsqrtf(vh + 1e-12f);
#pragma unroll
        for (int nt = 0; nt < 8; ++nt) {
            int c0 = nt * 8 + 2 * q4;
            float g0 = sP[256 + c0], g1v = sP[256 + c0 + 1];
            float e0 = sP[320 + c0], e1v = sP[320 + c0 + 1];
            float zl0 = fmaxf((a2[nt][0] - ml) * il * g0  + e0,  0.f);
            float zl1 = fmaxf((a2[nt][1] - ml) * il * g1v + e1v, 0.f);
            float zh0 = fmaxf((a2[nt][2] - mh) * ih * g0  + e0,  0.f);
            float zh1 = fmaxf((a2[nt][3] - mh) * ih * g1v + e1v, 0.f);
            *(unsigned*)(sX + ar * XPH + c0)       = h2u(zl0, zl1);
            *(unsigned*)(sX + (ar + 8) * XPH + c0) = h2u(zh0, zh1);
        }
    }
    __syncthreads();   // out-stage reads rows across warps

    // ---- out: gather fragment uint4s from sX, coalesced STG.128 ----
#pragma unroll
    for (int q = 0; q < 4; ++q) {
        int idx = tid + q * 256;
        int f = idx & 511, tj = idx >> 9;
        int l2 = f & 31, kt = (f >> 5) & 3, mtg = f >> 7;
        int sA = mtg * 16 + (l2 >> 2);
        int c0 = kt * 16 + 2 * (l2 & 3);
        const __half* bsx = sX + (tj * 64) * XPH;
        uint4 v;
        v.x = *(const unsigned*)(bsx + sA * XPH + c0);
        v.y = *(const unsigned*)(bsx + (sA + 8) * XPH + c0);
        v.z = *(const unsigned*)(bsx + sA * XPH + c0 + 8);
        v.w = *(const unsigned*)(bsx + (sA + 8) * XPH + c0 + 8);
        int t = tpair * 2 + tj;
        *(uint4*)(g_x2h + ((size_t)t * 64 + chunk) * 4096 + (size_t)f * 8) = v;
    }
}

// =====================================================================
// Kernel 2: bidirectional LSTM + fused attention. 32 seqs/CTA,
// grid (128, 2), 256 threads, 2 CTAs/SM. fp32 tanh.approx gates
// (known-good 4.9e-4); h stored before xs/ps reductions.
// =====================================================================
__global__ void __launch_bounds__(256, 2) lstm_kernel(
    const float* __restrict__ Wf, const float* __restrict__ bfv,
    const float* __restrict__ Wb, const float* __restrict__ bbv,
    const float* __restrict__ wx, const float* __restrict__ bxv,
    const float* __restrict__ wp, const float* __restrict__ bp,
    const float* __restrict__ gp, const float* __restrict__ bep,
    const float* __restrict__ W3, const float* __restrict__ b3,
    float* __restrict__ out)
{
    extern __shared__ char smc[];
    uint2*  wF  = (uint2*)smc;                      // 8192 uint2 (64 KB)
    __half* xb  = (__half*)(smc + 65536);           // 2 x 2048 halves
    __half* hT  = (__half*)(smc + 65536 + 8192);    // 2 x 2048 halves
    float*  red = (float*)(smc + 65536 + 16384);    // 2 x 512
    float*  sXS = (float*)(smc + 65536 + 20480);    // 32 x 65
    float*  sPS = sXS + 32 * 65;                    // 32 x 65

    const int dir = blockIdx.y;
    const int chk = blockIdx.x;
    const float* W    = dir ? Wb  : Wf;
    const float* bias = dir ? bbv : bfv;
    const int tid = threadIdx.x;
    const int l = tid & 31, w = tid >> 5;
    const int wu = w;
    const size_t xbase = ((size_t)(chk >> 1)) * 4096 + (size_t)(chk & 1) * 2048;

#pragma unroll
    for (int q = 0; q < 32; ++q) {
        int s = tid + q * 256;
        int l2 = s & 31, kt = (s >> 5) & 7, g = (s >> 8) & 3, ww = s >> 10;
        int k0 = kt * 16 + 2 * (l2 & 3);
        int n  = g * 64 + 8 * ww + (l2 >> 2);
        uint2 b;
        b.x = h2u(W[k0 * 256 + n],       W[(k0 + 1) * 256 + n]);
        b.y = h2u(W[(k0 + 8) * 256 + n], W[(k0 + 9) * 256 + n]);
        wF[s] = b;
    }
    {
        int t0 = dir ? 63 : 0;
        const uint4* src = (const uint4*)(g_x2h + (size_t)t0 * 64 * 4096 + xbase);
        ((uint4*)xb)[tid] = src[tid];
        ((uint4*)hT)[tid] = make_uint4(0, 0, 0, 0);
    }
    __syncthreads();

    uint2 bxr[4][4];
#pragma unroll
    for (int kt = 0; kt < 4; ++kt)
#pragma unroll
        for (int g = 0; g < 4; ++g)
            bxr[kt][g] = wF[((wu * 4 + g) * 8 + kt) * 32 + l];

    const int q4 = l & 3, rlq = l >> 2;
    const int u0 = 8 * wu + 2 * q4;
    float bia[4][2];
#pragma unroll
    for (int g = 0; g < 4; ++g) {
        bia[g][0] = bias[g * 64 + u0];
        bia[g][1] = bias[g * 64 + u0 + 1];
    }
    const float wxu0 = wx[u0], wxu1 = wx[u0 + 1];
    const float wpu0 = wp[u0], wpu1 = wp[u0 + 1];
    const float bxs = bxv[0], bps = bp[0];

    float cst[2][4];
#pragma unroll
    for (int mt = 0; mt < 2; ++mt)
#pragma unroll
        for (int s = 0; s < 4; ++s) cst[mt][s] = 0.f;

    const int kth = wu >> 1;
    const int hsl = (wu & 1) * 4;

    for (int st = 0; st < 64; ++st) {
        const int p = st & 1;
        __syncthreads();   // single barrier per step

        if (st > 0 && tid < 64) {
            int which = tid >> 5, seq = tid & 31;
            const float* rb = red + ((st - 1) & 1) * 512 + which * 256 + seq;
            float v = rb[0] + rb[32] + rb[64] + rb[96]
                    + rb[128] + rb[160] + rb[192] + rb[224];
            int tprev = dir ? (64 - st) : (st - 1);
            if (which) sPS[seq * 65 + tprev] = v + bps;
            else       sXS[seq * 65 + tprev] = v + bxs;
        }

        uint4 xpf;
        if (st < 63) {
            int t2 = dir ? (62 - st) : (st + 1);
            xpf = ((const uint4*)(g_x2h + (size_t)t2 * 64 * 4096 + xbase))[tid];
        }

        const __half* xbp = xb + p * 2048;
        const __half* hFp = hT + p * 2048;

        float acc[2][4][4];
#pragma unroll
        for (int mt = 0; mt < 2; ++mt)
#pragma unroll
            for (int g = 0; g < 4; ++g) {
                acc[mt][g][0] = bia[g][0]; acc[mt][g][1] = bia[g][1];
                acc[mt][g][2] = bia[g][0]; acc[mt][g][3] = bia[g][1];
            }

#pragma unroll
        for (int kt = 0; kt < 4; ++kt) {
#pragma unroll
            for (int mt = 0; mt < 2; ++mt) {
                uint4 a = *(const uint4*)(xbp + (((mt * 4 + kt) * 32 + l) << 3));
#pragma unroll
                for (int g = 0; g < 4; ++g)
                    mma_f16(acc[mt][g], a, bxr[kt][g]);
            }
        }
#pragma unroll
        for (int kt = 0; kt < 4; ++kt) {
#pragma unroll
            for (int mt = 0; mt < 2; ++mt) {
                uint4 a = *(const uint4*)(hFp + (((mt * 4 + kt) * 32 + l) << 3));
#pragma unroll
                for (int g = 0; g < 4; ++g)
                    mma_f16(acc[mt][g], a, wF[((wu * 4 + g) * 8 + 4 + kt) * 32 + l]);
            }
        }

        // ---- epilogue: fp32 gates (known-good); h stored first ----
        float hreg[2][4];
#pragma unroll
        for (int mt = 0; mt < 2; ++mt) {
#pragma unroll
            for (int s = 0; s < 4; ++s) {
                float iv = acc[mt][0][s], jv = acc[mt][1][s];
                float fv = acc[mt][2][s], ov = acc[mt][3][s];
                float cn = cst[mt][s] * sigt(fv + 1.f) + sigt(iv) * tanha(jv);
                cst[mt][s] = cn;
                hreg[mt][s] = tanha(cn) * sigt(ov);
            }
            // store h immediately (shortens next-step dependency chain)
            __half* hDst = hT + (p ^ 1) * 2048;
            uint2 hv;
            hv.x = h2u(hreg[mt][0], hreg[mt][1]);
            hv.y = h2u(hreg[mt][2], hreg[mt][3]);
            *(uint2*)(hDst + (((mt * 4 + kth) * 32 + l) << 3) + hsl) = hv;
        }
        // prefetched x -> xb[p^1]
        if (st < 63) {
            ((uint4*)(xb + (p ^ 1) * 2048))[tid] = xpf;
        }

        // xs/ps partials
        float px[2][2], pq[2][2];
#pragma unroll
        for (int mt = 0; mt < 2; ++mt) {
            px[mt][0] = hreg[mt][0] * wxu0 + hreg[mt][1] * wxu1;
            px[mt][1] = hreg[mt][2] * wxu0 + hreg[mt][3] * wxu1;
            pq[mt][0] = hreg[mt][0] * wpu0 + hreg[mt][1] * wpu1;
            pq[mt][1] = hreg[mt][2] * wpu0 + hreg[mt][3] * wpu1;
        }
#pragma unroll
        for (int o = 1; o <= 2; o <<= 1) {
#pragma unroll
            for (int mt = 0; mt < 2; ++mt) {
                px[mt][0] += __shfl_xor_sync(0xffffffffu, px[mt][0], o);
                px[mt][1] += __shfl_xor_sync(0xffffffffu, px[mt][1], o);
                pq[mt][0] += __shfl_xor_sync(0xffffffffu, pq[mt][0], o);
                pq[mt][1] += __shfl_xor_sync(0xffffffffu, pq[mt][1], o);
            }
        }
        if ((l & 3) == 0) {
            float* rp = red + p * 512;
#pragma unroll
            for (int mt = 0; mt < 2; ++mt) {
                int seqlo = mt * 16 + (l >> 2);
                rp[wu * 32 + seqlo]           = px[mt][0];
                rp[wu * 32 + seqlo + 8]       = px[mt][1];
                rp[256 + wu * 32 + seqlo]     = pq[mt][0];
                rp[256 + wu * 32 + seqlo + 8] = pq[mt][1];
            }
        }
    }

    // ---- final drain + attn params (reuse wF region) ----
    __syncthreads();
    if (tid < 64) {
        int which = tid >> 5, seq = tid & 31;
        const float* rb = red + 512 + which * 256 + seq;   // st=63 parity 1
        float v = rb[0] + rb[32] + rb[64] + rb[96]
                + rb[128] + rb[160] + rb[192] + rb[224];
        int tlast = dir ? 0 : 63;
        if (which) sPS[seq * 65 + tlast] = v + bps;
        else       sXS[seq * 65 + tlast] = v + bxs;
    }
    float* sW3a = (float*)smc;
    float* sprm = sW3a + 4096;
    for (int i = tid; i < 1024; i += 256) ((float4*)sW3a)[i] = ((const float4*)W3)[i];
    if (tid < 64) {
        sprm[tid]       = b3[tid];
        sprm[64 + tid]  = gp[tid];
        sprm[128 + tid] = bep[tid];
    }
    __syncthreads();

    // ---- fused attention: 8 warps x 4 seqs = 32 ----
#pragma unroll
    for (int si = 0; si < 4; ++si) {
        int seq = w * 4 + si;
        float v0 = sPS[seq * 65 + l], v1 = sPS[seq * 65 + 32 + l];
        float s = v0 + v1, q = v0 * v0 + v1 * v1;
#pragma unroll
        for (int o = 16; o; o >>= 1) {
            s += __shfl_xor_sync(0xffffffffu, s, o);
            q += __shfl_xor_sync(0xffffffffu, q, o);
        }
        float m = s * 0.015625f;
        float var = q * 0.015625f - m * m;
        float rs = rsqrtf(var + 1e-12f);
        float p0 = fmaxf((v0 - m) * rs * sprm[64 + l] + sprm[128 + l], 0.f);
        float p1 = fmaxf((v1 - m) * rs * sprm[96 + l] + sprm[160 + l], 0.f);

        float l0 = sprm[l], l1 = sprm[32 + l];
#pragma unroll 8
        for (int tt = 0; tt < 32; ++tt) {
            float pv = __shfl_sync(0xffffffffu, p0, tt);
            l0 += pv * sW3a[tt * 64 + l];
            l1 += pv * sW3a[tt * 64 + 32 + l];
        }
#pragma unroll 8
        for (int tt = 0; tt < 32; ++tt) {
            float pv = __shfl_sync(0xffffffffu, p1, tt);
            l0 += pv * sW3a[(32 + tt) * 64 + l];
            l1 += pv * sW3a[(32 + tt) * 64 + 32 + l];
        }

        float mx = fmaxf(l0, l1);
#pragma unroll
        for (int o = 16; o; o >>= 1) mx = fmaxf(mx, __shfl_xor_sync(0xffffffffu, mx, o));
        float e0 = __expf(l0 - mx), e1 = __expf(l1 - mx);
        float se = e0 + e1;
        float rsum = e0 * sXS[seq * 65 + l] + e1 * sXS[seq * 65 + 32 + l];
#pragma unroll
        for (int o = 16; o; o >>= 1) {
            se   += __shfl_xor_sync(0xffffffffu, se, o);
            rsum += __shfl_xor_sync(0xffffffffu, rsum, o);
        }
        if (l == 0) out[(size_t)dir * Bn + chk * 32 + seq] = rsum / se;
    }
}

// =====================================================================
extern "C" void kernel_launch(void* const* d_in, const int* in_sizes, int n_in,
                              void* d_out, int out_size)
{
    const float* obs = (const float*)d_in[0];
    const float* act = (const float*)d_in[1];
    const float* W1  = (const float*)d_in[2];
    const float* b1  = (const float*)d_in[3];
    const float* g1  = (const float*)d_in[4];
    const float* be1 = (const float*)d_in[5];
    const float* W2  = (const float*)d_in[6];
    const float* b2  = (const float*)d_in[7];
    const float* g2  = (const float*)d_in[8];
    const float* be2 = (const float*)d_in[9];
    const float* Wf  = (const float*)d_in[10];
    const float* bf  = (const float*)d_in[11];
    const float* Wb  = (const float*)d_in[12];
    const float* bb  = (const float*)d_in[13];
    const float* wx  = (const float*)d_in[14];
    const float* bxv = (const float*)d_in[15];
    const float* wp  = (const float*)d_in[16];
    const float* bp  = (const float*)d_in[17];
    const float* gp  = (const float*)d_in[18];
    const float* bep = (const float*)d_in[19];
    const float* W3  = (const float*)d_in[20];
    const float* b3  = (const float*)d_in[21];
    float* out = (float*)d_out;

    const int trunk_smem = 28672 + 128 * XPH * 2 + 128 * AP * 2 + 384 * 4;   // 75264 B
    const int lstm_smem  = 65536 + 8192 + 8192 + 4096 + 2 * 32 * 65 * 4;     // 102656 B
    cudaFuncSetAttribute(trunk_kernel, cudaFuncAttributeMaxDynamicSharedMemorySize, trunk_smem);
    cudaFuncSetAttribute(lstm_kernel,  cudaFuncAttributeMaxDynamicSharedMemorySize, lstm_smem);

    trunk_kernel<<<2048, 256, trunk_smem>>>(obs, act, W1, b1, g1, be1, W2, b2, g2, be2);

    dim3 lg(128, 2);
    lstm_kernel<<<lg, 256, lstm_smem>>>(Wf, bf, Wb, bb, wx, bxv, wp, bp,
                                        gp, bep, W3, b3, out);
}